// round 9
// baseline (speedup 1.0000x reference)
#include <cuda_runtime.h>
#include <cuda_bf16.h>

#define NRES 1024
#define CZ   128
#define NB   65

// out[i][j][c] = W[c][idx(i,j)] + b[c]
// idx(i,j) = 0 if i==j else clamp(round_half_down(r[j]-r[i]), -32, 32) + 32
__global__ __launch_bounds__(256, 4)
void relpos_kernel(const float* __restrict__ r,
                   const float* __restrict__ W,
                   const float* __restrict__ b,
                   float4* __restrict__ out) {
    __shared__ float lut[NB * CZ];   // 33,280 B : lut[k*CZ + c] = W[c][k] + b[c]
    __shared__ float rs[NRES];       //  4,096 B

    const int tid = threadIdx.x;

    // Build LUT (65*128 = 8320 elems; W row-major [CZ, NB])
    for (int x = tid; x < NB * CZ; x += blockDim.x) {
        int k = x / CZ;
        int c = x - k * CZ;
        lut[x] = W[c * NB + k] + b[c];
    }
    // Cache residue_index
    for (int x = tid; x < NRES; x += blockDim.x) rs[x] = r[x];
    __syncthreads();

    const int i  = blockIdx.x;
    const float ri = rs[i];
    const float4* __restrict__ lut4 = (const float4*)lut;     // [NB][32]
    float4* __restrict__ orow = out + (size_t)i * NRES * (CZ / 4);

    const int v    = tid & 31;   // float4 lane within a row of 128 channels
    const int jsub = tid >> 5;   // warp id -> j offset (8 warps)

    #pragma unroll 4
    for (int j = jsub; j < NRES; j += 8) {
        int idx;
        if (j == i) {
            idx = 0;  // diagonal: all-inf distances -> argmin returns 0
        } else {
            float d  = rs[j] - ri;
            float kf = ceilf(d - 0.5f);            // round-half-down (argmin tie -> lower bin)
            kf = fminf(fmaxf(kf, -32.0f), 32.0f);
            idx = (int)kf + 32;
        }
        // Warp-coalesced 512B store of the looked-up channel vector
        orow[(size_t)j * (CZ / 4) + v] = lut4[idx * (CZ / 4) + v];
    }
}

extern "C" void kernel_launch(void* const* d_in, const int* in_sizes, int n_in,
                              void* d_out, int out_size) {
    const float* r = (const float*)d_in[0];   // residue_index [1024]
    const float* W = (const float*)d_in[1];   // [128, 65]
    const float* b = (const float*)d_in[2];   // [128]
    float4* out = (float4*)d_out;             // [1024, 1024, 128] fp32

    relpos_kernel<<<NRES, 256>>>(r, W, b, out);
}